// round 1
// baseline (speedup 1.0000x reference)
#include <cuda_runtime.h>
#include <math.h>

#define BATCH 16
#define SEQ   784
#define DIMV  768
#define NHEAD 12
#define HDIM  64
#define TOK   (BATCH*SEQ)   // 12544
#define F3    (3*DIMV)      // 2304

// Scratch (device globals: allocation-free)
__device__ float g_q[(size_t)BATCH*NHEAD*SEQ*HDIM];
__device__ float g_k[(size_t)BATCH*NHEAD*SEQ*HDIM];
__device__ float g_v[(size_t)BATCH*NHEAD*SEQ*HDIM];
__device__ float g_attn[(size_t)TOK*DIMV];

// ---------------------------------------------------------------------------
// SGEMM: C[M,N] = A[M,K] @ B[K,N] + bias[N]
// BM=BN=128, BK=16, 256 threads, 8x8 per thread.
// SCATTER=true: writes to g_q/g_k/g_v in [b][h][n][d] layout instead of C.
// All dims are exact multiples of the tile sizes (12544/128, 2304/128, 768/128,
// 768/16) so no bounds checks.
// ---------------------------------------------------------------------------
template<bool SCATTER>
__global__ __launch_bounds__(256)
void sgemm_kernel(const float* __restrict__ A, const float* __restrict__ B,
                  const float* __restrict__ bias, float* __restrict__ C,
                  int M, int N, int K)
{
    __shared__ float As[16][132];   // transposed A tile, padded
    __shared__ float Bs[16][128];

    const int bm  = blockIdx.y * 128;
    const int bn  = blockIdx.x * 128;
    const int tid = threadIdx.x;
    const int tm0 = (tid >> 4) * 8;
    const int tn0 = (tid & 15) * 8;

    float acc[8][8];
#pragma unroll
    for (int i = 0; i < 8; i++)
#pragma unroll
        for (int j = 0; j < 8; j++) acc[i][j] = 0.f;

    const int arow0 = tid >> 2, ac4 = tid & 3;     // A: 128 rows x 4 float4
    const int brow0 = tid >> 5, bc4 = tid & 31;    // B: 16 rows x 32 float4

    for (int k0 = 0; k0 < K; k0 += 16) {
#pragma unroll
        for (int r = 0; r < 2; r++) {
            int row = arow0 + r * 64;
            const float4 va = *(const float4*)(A + (size_t)(bm + row) * K + k0 + ac4 * 4);
            As[ac4*4+0][row] = va.x;
            As[ac4*4+1][row] = va.y;
            As[ac4*4+2][row] = va.z;
            As[ac4*4+3][row] = va.w;
        }
#pragma unroll
        for (int r = 0; r < 2; r++) {
            int row = brow0 + r * 8;
            *(float4*)(&Bs[row][bc4*4]) =
                *(const float4*)(B + (size_t)(k0 + row) * N + bn + bc4 * 4);
        }
        __syncthreads();

#pragma unroll
        for (int k = 0; k < 16; k++) {
            float a[8], b[8];
            *(float4*)&a[0] = *(const float4*)&As[k][tm0];
            *(float4*)&a[4] = *(const float4*)&As[k][tm0+4];
            *(float4*)&b[0] = *(const float4*)&Bs[k][tn0];
            *(float4*)&b[4] = *(const float4*)&Bs[k][tn0+4];
#pragma unroll
            for (int i = 0; i < 8; i++)
#pragma unroll
                for (int j = 0; j < 8; j++)
                    acc[i][j] += a[i] * b[j];
        }
        __syncthreads();
    }

    const int col0 = bn + tn0;
#pragma unroll
    for (int i = 0; i < 8; i++) {
        int row = bm + tm0 + i;
        float4 v0 = make_float4(acc[i][0] + bias[col0+0], acc[i][1] + bias[col0+1],
                                acc[i][2] + bias[col0+2], acc[i][3] + bias[col0+3]);
        float4 v1 = make_float4(acc[i][4] + bias[col0+4], acc[i][5] + bias[col0+5],
                                acc[i][6] + bias[col0+6], acc[i][7] + bias[col0+7]);
        if (SCATTER) {
            // col0..col0+7 lie within one (s,h) because tn0 % 8 == 0 and 8 | 64
            int bb  = row / SEQ;
            int n   = row - bb * SEQ;
            int s   = col0 / DIMV;
            int rem = col0 - s * DIMV;
            int hh  = rem / HDIM;
            int d   = rem - hh * HDIM;
            float* base = (s == 0) ? g_q : ((s == 1) ? g_k : g_v);
            float* dst = base + (((size_t)bb * NHEAD + hh) * SEQ + n) * HDIM + d;
            *(float4*)dst       = v0;
            *(float4*)(dst + 4) = v1;
        } else {
            float* dst = C + (size_t)row * N + col0;
            *(float4*)dst       = v0;
            *(float4*)(dst + 4) = v1;
        }
    }
}

// ---------------------------------------------------------------------------
// Flash attention: one CTA per (b*h, 128-row i-tile). j-tiles of 64.
// 256 threads as 16x16: each thread owns 8 rows x 4 cols.
// Smem: Q[128][68], KP[128][68] (K tile, later aliased by P), V[64][68].
// Output written to g_attn in [b][n][h*64+d] layout (ready for out-proj GEMM).
// ---------------------------------------------------------------------------
#define APAD 68
#define ATTN_SMEM ((size_t)(128 + 128 + 64) * APAD * sizeof(float))

__global__ __launch_bounds__(256)
void attn_kernel()
{
    extern __shared__ float sm[];
    float (*Qs)[APAD]  = (float(*)[APAD])sm;
    float (*KPs)[APAD] = (float(*)[APAD])(sm + 128 * APAD);
    float (*Vs)[APAD]  = (float(*)[APAD])(sm + 256 * APAD);

    const int bh = blockIdx.y;
    const int b  = bh / NHEAD;
    const int h  = bh - b * NHEAD;
    const int i0 = blockIdx.x * 128;
    const int tid = threadIdx.x;
    const int tm0 = (tid >> 4) * 8;
    const int tn0 = (tid & 15) * 4;
    const float scale = 0.125f;  // 64^-0.5

    const float* qb = g_q + (size_t)bh * SEQ * HDIM;
    const float* kb = g_k + (size_t)bh * SEQ * HDIM;
    const float* vb = g_v + (size_t)bh * SEQ * HDIM;

    // Load Q tile (scaled); zero-fill padded rows
#pragma unroll
    for (int it = 0; it < 8; it++) {
        int id  = tid + it * 256;
        int row = id >> 4, c4 = id & 15;
        int n   = i0 + row;
        float4 v = make_float4(0.f, 0.f, 0.f, 0.f);
        if (n < SEQ) v = *(const float4*)(qb + (size_t)n * HDIM + c4 * 4);
        v.x *= scale; v.y *= scale; v.z *= scale; v.w *= scale;
        *(float4*)&Qs[row][c4 * 4] = v;
    }

    float acc[8][4], m_i[8], l_i[8];
#pragma unroll
    for (int i = 0; i < 8; i++) {
        m_i[i] = -INFINITY; l_i[i] = 0.f;
        acc[i][0] = acc[i][1] = acc[i][2] = acc[i][3] = 0.f;
    }

    for (int j0 = 0; j0 < SEQ; j0 += 64) {
        __syncthreads();   // previous PV done reading KP/V
        // Load K, V j-tiles (zero-fill padded rows)
#pragma unroll
        for (int it = 0; it < 4; it++) {
            int id  = tid + it * 256;
            int row = id >> 4, c4 = id & 15;
            int n   = j0 + row;
            float4 kv = make_float4(0.f, 0.f, 0.f, 0.f);
            float4 vv = kv;
            if (n < SEQ) {
                kv = *(const float4*)(kb + (size_t)n * HDIM + c4 * 4);
                vv = *(const float4*)(vb + (size_t)n * HDIM + c4 * 4);
            }
            *(float4*)&KPs[row][c4 * 4] = kv;
            *(float4*)&Vs[row][c4 * 4]  = vv;
        }
        __syncthreads();

        // S = (Q*scale) @ K^T  for this 128x64 tile
        float s[8][4];
#pragma unroll
        for (int i = 0; i < 8; i++) s[i][0] = s[i][1] = s[i][2] = s[i][3] = 0.f;

#pragma unroll
        for (int d4 = 0; d4 < 16; d4++) {
            float4 k0r = *(const float4*)&KPs[tn0 + 0][d4 * 4];
            float4 k1r = *(const float4*)&KPs[tn0 + 1][d4 * 4];
            float4 k2r = *(const float4*)&KPs[tn0 + 2][d4 * 4];
            float4 k3r = *(const float4*)&KPs[tn0 + 3][d4 * 4];
#pragma unroll
            for (int i = 0; i < 8; i++) {
                float4 q = *(const float4*)&Qs[tm0 + i][d4 * 4];
                s[i][0] += q.x*k0r.x + q.y*k0r.y + q.z*k0r.z + q.w*k0r.w;
                s[i][1] += q.x*k1r.x + q.y*k1r.y + q.z*k1r.z + q.w*k1r.w;
                s[i][2] += q.x*k2r.x + q.y*k2r.y + q.z*k2r.z + q.w*k2r.w;
                s[i][3] += q.x*k3r.x + q.y*k3r.y + q.z*k3r.z + q.w*k3r.w;
            }
        }

        // Online softmax update (row reductions across the 16 tx lanes)
        const bool tail = (j0 + 64 > SEQ);
#pragma unroll
        for (int i = 0; i < 8; i++) {
            if (tail) {
#pragma unroll
                for (int j = 0; j < 4; j++)
                    if (j0 + tn0 + j >= SEQ) s[i][j] = -INFINITY;
            }
            float mx = fmaxf(fmaxf(s[i][0], s[i][1]), fmaxf(s[i][2], s[i][3]));
            mx = fmaxf(mx, __shfl_xor_sync(0xffffffffu, mx, 1));
            mx = fmaxf(mx, __shfl_xor_sync(0xffffffffu, mx, 2));
            mx = fmaxf(mx, __shfl_xor_sync(0xffffffffu, mx, 4));
            mx = fmaxf(mx, __shfl_xor_sync(0xffffffffu, mx, 8));
            float mnew = fmaxf(m_i[i], mx);
            float corr = __expf(m_i[i] - mnew);
            float rs = 0.f;
#pragma unroll
            for (int j = 0; j < 4; j++) {
                float p = __expf(s[i][j] - mnew);
                s[i][j] = p; rs += p;
            }
            rs += __shfl_xor_sync(0xffffffffu, rs, 1);
            rs += __shfl_xor_sync(0xffffffffu, rs, 2);
            rs += __shfl_xor_sync(0xffffffffu, rs, 4);
            rs += __shfl_xor_sync(0xffffffffu, rs, 8);
            l_i[i] = l_i[i] * corr + rs;
            m_i[i] = mnew;
            acc[i][0] *= corr; acc[i][1] *= corr;
            acc[i][2] *= corr; acc[i][3] *= corr;
        }

        __syncthreads();   // all threads done reading K tile
        // Stage P (aliases over K buffer; P is 128 rows)
#pragma unroll
        for (int i = 0; i < 8; i++) {
            float4 pp = make_float4(s[i][0], s[i][1], s[i][2], s[i][3]);
            *(float4*)&KPs[tm0 + i][tn0] = pp;
        }
        __syncthreads();

        // acc += P @ V
#pragma unroll
        for (int c4 = 0; c4 < 16; c4++) {
            float4 v0 = *(const float4*)&Vs[c4 * 4 + 0][tn0];
            float4 v1 = *(const float4*)&Vs[c4 * 4 + 1][tn0];
            float4 v2 = *(const float4*)&Vs[c4 * 4 + 2][tn0];
            float4 v3 = *(const float4*)&Vs[c4 * 4 + 3][tn0];
#pragma unroll
            for (int i = 0; i < 8; i++) {
                float4 p = *(const float4*)&KPs[tm0 + i][c4 * 4];
                acc[i][0] += p.x*v0.x + p.y*v1.x + p.z*v2.x + p.w*v3.x;
                acc[i][1] += p.x*v0.y + p.y*v1.y + p.z*v2.y + p.w*v3.y;
                acc[i][2] += p.x*v0.z + p.y*v1.z + p.z*v2.z + p.w*v3.z;
                acc[i][3] += p.x*v0.w + p.y*v1.w + p.z*v2.w + p.w*v3.w;
            }
        }
    }

    // Write O / l  into [b][n][h*64+d] layout
#pragma unroll
    for (int i = 0; i < 8; i++) {
        int n = i0 + tm0 + i;
        if (n < SEQ) {
            float inv = 1.0f / l_i[i];
            float4 o = make_float4(acc[i][0]*inv, acc[i][1]*inv,
                                   acc[i][2]*inv, acc[i][3]*inv);
            *(float4*)(g_attn + ((size_t)b * SEQ + n) * DIMV + h * HDIM + tn0) = o;
        }
    }
}

// ---------------------------------------------------------------------------
extern "C" void kernel_launch(void* const* d_in, const int* in_sizes, int n_in,
                              void* d_out, int out_size)
{
    const float* x    = (const float*)d_in[0];
    const float* Wqkv = (const float*)d_in[1];
    const float* bqkv = (const float*)d_in[2];
    const float* Wo   = (const float*)d_in[3];
    const float* bo   = (const float*)d_in[4];
    float* out = (float*)d_out;

    float* pattn = nullptr;
    cudaGetSymbolAddress((void**)&pattn, g_attn);

    // 1) QKV projection + scatter into q/k/v [b][h][n][d]
    sgemm_kernel<true><<<dim3(F3 / 128, TOK / 128), 256>>>(
        x, Wqkv, bqkv, nullptr, TOK, F3, DIMV);

    // 2) Flash attention
    cudaFuncSetAttribute(attn_kernel,
                         cudaFuncAttributeMaxDynamicSharedMemorySize,
                         (int)ATTN_SMEM);
    attn_kernel<<<dim3((SEQ + 127) / 128, BATCH * NHEAD), 256, ATTN_SMEM>>>();

    // 3) Output projection
    sgemm_kernel<false><<<dim3(DIMV / 128, TOK / 128), 256>>>(
        pattn, Wo, bo, out, TOK, DIMV, DIMV);
}

// round 7
// speedup vs baseline: 1.3869x; 1.3869x over previous
#include <cuda_runtime.h>
#include <cuda_bf16.h>
#include <cstdint>
#include <math.h>

#define BATCH 16
#define SEQ   784
#define DIMV  768
#define NHEAD 12
#define HDIM  64
#define TOK   (BATCH*SEQ)   // 12544
#define F3    (3*DIMV)      // 2304

// ---------------- scratch (device globals; allocation-free) ----------------
__device__ float g_q[(size_t)BATCH*NHEAD*SEQ*HDIM];
__device__ float g_k[(size_t)BATCH*NHEAD*SEQ*HDIM];
__device__ float g_v[(size_t)BATCH*NHEAD*SEQ*HDIM];
__device__ __align__(16) __nv_bfloat16 g_xh[(size_t)TOK*DIMV];
__device__ __align__(16) __nv_bfloat16 g_xl[(size_t)TOK*DIMV];
__device__ __align__(16) __nv_bfloat16 g_wqh[(size_t)F3*DIMV];   // [2304][768] (transposed)
__device__ __align__(16) __nv_bfloat16 g_wql[(size_t)F3*DIMV];
__device__ __align__(16) __nv_bfloat16 g_woh[(size_t)DIMV*DIMV]; // [768][768] (transposed)
__device__ __align__(16) __nv_bfloat16 g_wol[(size_t)DIMV*DIMV];
__device__ __align__(16) __nv_bfloat16 g_ah[(size_t)TOK*DIMV];   // attention out hi
__device__ __align__(16) __nv_bfloat16 g_al[(size_t)TOK*DIMV];   // attention out lo

// ---------------- helpers (baseline PTX only: sm_80+ features) -------------
__device__ __forceinline__ uint32_t smem_u32(const void* p) {
    uint32_t a;
    asm("{ .reg .u64 t; cvta.to.shared.u64 t, %1; cvt.u32.u64 %0, t; }" : "=r"(a) : "l"(p));
    return a;
}
__device__ __forceinline__ void cp_async16(uint32_t dst, const void* src) {
    asm volatile("cp.async.cg.shared.global [%0], [%1], 16;" :: "r"(dst), "l"(src));
}
__device__ __forceinline__ void cp_commit() {
    asm volatile("cp.async.commit_group;" ::: "memory");
}
template<int N>
__device__ __forceinline__ void cp_wait() {
    asm volatile("cp.async.wait_group %0;" :: "n"(N) : "memory");
}
__device__ __forceinline__ uint32_t lds32(uint32_t addr) {
    uint32_t v;
    asm volatile("ld.shared.b32 %0, [%1];" : "=r"(v) : "r"(addr));
    return v;
}
// D = A(16x16 bf16, row) * B(16x8 bf16, col) + D  (fp32 accum)
__device__ __forceinline__ void mma16816(float* c, const uint32_t* a, uint32_t b0, uint32_t b1) {
    asm volatile(
        "mma.sync.aligned.m16n8k16.row.col.f32.bf16.bf16.f32 "
        "{%0,%1,%2,%3}, {%4,%5,%6,%7}, {%8,%9}, {%0,%1,%2,%3};"
        : "+f"(c[0]), "+f"(c[1]), "+f"(c[2]), "+f"(c[3])
        : "r"(a[0]), "r"(a[1]), "r"(a[2]), "r"(a[3]), "r"(b0), "r"(b1));
}

// ---------------------------------------------------------------------------
// Split kernels: fp32 -> bf16 hi/lo (residual) pairs
// ---------------------------------------------------------------------------
__global__ __launch_bounds__(256)
void split_x_kernel(const float4* __restrict__ x,
                    __nv_bfloat162* __restrict__ xh, __nv_bfloat162* __restrict__ xl, int n4)
{
    int i = blockIdx.x * 256 + threadIdx.x;
    if (i >= n4) return;
    float4 v = x[i];
    __nv_bfloat16 h0 = __float2bfloat16(v.x), h1 = __float2bfloat16(v.y);
    __nv_bfloat16 h2 = __float2bfloat16(v.z), h3 = __float2bfloat16(v.w);
    __nv_bfloat16 l0 = __float2bfloat16(v.x - __bfloat162float(h0));
    __nv_bfloat16 l1 = __float2bfloat16(v.y - __bfloat162float(h1));
    __nv_bfloat16 l2 = __float2bfloat16(v.z - __bfloat162float(h2));
    __nv_bfloat16 l3 = __float2bfloat16(v.w - __bfloat162float(h3));
    xh[2*i]   = __halves2bfloat162(h0, h1);
    xh[2*i+1] = __halves2bfloat162(h2, h3);
    xl[2*i]   = __halves2bfloat162(l0, l1);
    xl[2*i+1] = __halves2bfloat162(l2, l3);
}

// W [K_][N_] fp32 -> Th/Tl [N_][K_] bf16 (transpose + split)
__global__ __launch_bounds__(256)
void tsplit_kernel(const float* __restrict__ W,
                   __nv_bfloat16* __restrict__ Th, __nv_bfloat16* __restrict__ Tl,
                   int K_, int N_)
{
    __shared__ float t[32][33];
    int n0 = blockIdx.x * 32, k0 = blockIdx.y * 32;
    int tx = threadIdx.x & 31, ty = threadIdx.x >> 5;
#pragma unroll
    for (int r = 0; r < 4; r++)
        t[ty + r*8][tx] = W[(size_t)(k0 + ty + r*8) * N_ + n0 + tx];
    __syncthreads();
#pragma unroll
    for (int r = 0; r < 4; r++) {
        float v = t[tx][ty + r*8];
        __nv_bfloat16 h = __float2bfloat16(v);
        __nv_bfloat16 l = __float2bfloat16(v - __bfloat162float(h));
        size_t o = (size_t)(n0 + ty + r*8) * K_ + k0 + tx;
        Th[o] = h; Tl[o] = l;
    }
}

// ---------------------------------------------------------------------------
// mma.sync bf16x3 GEMM: C[128,128-tile] = A @ B^T + bias (fp32-accurate).
// A: [M][K] bf16 hi/lo (K-major). B: [N][K] bf16 hi/lo (K-major).
// CTA 128x128, BK=32, 8 warps (4 along M x 2 along N), warp tile 32x64.
// cp.async double-buffered. 80B-padded smem rows: conflict-free frag loads.
// SCATTER=1: QKV epilogue scattering into g_q/g_k/g_v ([b][h][n][d]).
// ---------------------------------------------------------------------------
#define GBK     32
#define NCHUNK  (DIMV / GBK)          // 24
#define ROWB    80                    // 32 bf16 (64B) + 16B pad
#define TILE_B  (128 * ROWB)          // 10240
#define STAGE_B (4 * TILE_B)          // 40960: Ah, Al, Bh, Bl
#define GEMM_SMEM (2 * STAGE_B)       // 81920

template<int SCATTER>
__global__ __launch_bounds__(256)
void bgemm_kernel(const __nv_bfloat16* __restrict__ Ah, const __nv_bfloat16* __restrict__ Al,
                  const __nv_bfloat16* __restrict__ Bh, const __nv_bfloat16* __restrict__ Bl,
                  const float* __restrict__ bias, float* __restrict__ C, int K)
{
    extern __shared__ char sm[];
    const uint32_t sb = smem_u32(sm);
    const int tid  = threadIdx.x;
    const int wid  = tid >> 5, lane = tid & 31;
    const int wm   = wid & 3, wn = wid >> 2;      // 4 x 2 warp grid
    const int tr   = lane >> 2;                   // 0..7
    const int tc   = (lane & 3) * 2;              // 0,2,4,6
    const int bm   = blockIdx.y * 128, bn = blockIdx.x * 128;

    const __nv_bfloat16* bases[4] = {
        Ah + (size_t)bm * K, Al + (size_t)bm * K,
        Bh + (size_t)bn * K, Bl + (size_t)bn * K };

    // issue loads of chunk `c` into stage `p`
    auto issue = [&](int c, int p) {
        const int k0 = c * GBK;
#pragma unroll
        for (int t = 0; t < 4; t++) {
#pragma unroll
            for (int i = 0; i < 2; i++) {
                int idx = tid + i * 256;          // 0..511
                int row = idx >> 2, c8 = idx & 3; // 128 rows x 4 x (8 bf16)
                cp_async16(sb + p * STAGE_B + t * TILE_B + row * ROWB + c8 * 16,
                           bases[t] + (size_t)row * K + k0 + c8 * 8);
            }
        }
        cp_commit();
    };

    float acc[2][8][4];
#pragma unroll
    for (int mi = 0; mi < 2; mi++)
#pragma unroll
        for (int ni = 0; ni < 8; ni++)
#pragma unroll
            for (int j = 0; j < 4; j++) acc[mi][ni][j] = 0.f;

    issue(0, 0);

    for (int c = 0; c < NCHUNK; c++) {
        const int p = c & 1;
        if (c + 1 < NCHUNK) { issue(c + 1, p ^ 1); cp_wait<1>(); }
        else                { cp_wait<0>(); }
        __syncthreads();

        const uint32_t stg = sb + p * STAGE_B;
#pragma unroll
        for (int k16 = 0; k16 < GBK; k16 += 16) {
            // A fragments (hi & lo), 2 m-frags each
            uint32_t ah[2][4], al[2][4];
#pragma unroll
            for (int mi = 0; mi < 2; mi++) {
                const int m = wm * 32 + mi * 16;
                const uint32_t o00 = stg + (m + tr)     * ROWB + (k16 + tc) * 2;
                const uint32_t o10 = stg + (m + tr + 8) * ROWB + (k16 + tc) * 2;
                ah[mi][0] = lds32(o00);
                ah[mi][1] = lds32(o10);
                ah[mi][2] = lds32(o00 + 16);
                ah[mi][3] = lds32(o10 + 16);
                al[mi][0] = lds32(o00 + TILE_B);
                al[mi][1] = lds32(o10 + TILE_B);
                al[mi][2] = lds32(o00 + 16 + TILE_B);
                al[mi][3] = lds32(o10 + 16 + TILE_B);
            }
#pragma unroll
            for (int ni = 0; ni < 8; ni++) {
                const int n = wn * 64 + ni * 8;
                const uint32_t ob = stg + 2 * TILE_B + (n + tr) * ROWB + (k16 + tc) * 2;
                uint32_t bh0 = lds32(ob),          bh1 = lds32(ob + 16);
                uint32_t bl0 = lds32(ob + TILE_B), bl1 = lds32(ob + TILE_B + 16);
#pragma unroll
                for (int mi = 0; mi < 2; mi++) {
                    mma16816(acc[mi][ni], ah[mi], bh0, bh1);
                    mma16816(acc[mi][ni], al[mi], bh0, bh1);
                    mma16816(acc[mi][ni], ah[mi], bl0, bl1);
                }
            }
        }
        __syncthreads();
    }

    // Epilogue: c0,c1 -> row (tr), cols (tc, tc+1); c2,c3 -> row (tr+8)
#pragma unroll
    for (int mi = 0; mi < 2; mi++) {
#pragma unroll
        for (int ni = 0; ni < 8; ni++) {
            const int r0  = bm + wm * 32 + mi * 16 + tr;
            const int col = bn + wn * 64 + ni * 8 + tc;
            const float b0 = bias[col], b1 = bias[col + 1];
            float2 v0 = make_float2(acc[mi][ni][0] + b0, acc[mi][ni][1] + b1);
            float2 v1 = make_float2(acc[mi][ni][2] + b0, acc[mi][ni][3] + b1);
            if (SCATTER) {
                int bb = r0 / SEQ;                 // same batch for r0 and r0+8? not
                // compute separately per row (r0 and r0+8 may straddle batches)
                int s   = col / DIMV;
                int rem = col - s * DIMV;
                int hh  = rem >> 6, d0 = rem & 63;
                float* base = (s == 0) ? g_q : ((s == 1) ? g_k : g_v);
                {
                    int n = r0 - bb * SEQ;
                    *(float2*)(base + (((size_t)bb * NHEAD + hh) * SEQ + n) * HDIM + d0) = v0;
                }
                {
                    int r1 = r0 + 8;
                    int bb1 = r1 / SEQ;
                    int n1 = r1 - bb1 * SEQ;
                    *(float2*)(base + (((size_t)bb1 * NHEAD + hh) * SEQ + n1) * HDIM + d0) = v1;
                }
            } else {
                *(float2*)(C + (size_t)r0 * DIMV + col)       = v0;
                *(float2*)(C + (size_t)(r0 + 8) * DIMV + col) = v1;
            }
        }
    }
}

// ---------------------------------------------------------------------------
// Flash attention (SIMT fp32, proven): one CTA per (b*h, 128-row i-tile).
// Epilogue writes bf16 hi/lo directly for the out-projection GEMM.
// ---------------------------------------------------------------------------
#define APAD 68
#define ATTN_SMEM ((size_t)(128 + 128 + 64) * APAD * sizeof(float))

__global__ __launch_bounds__(256)
void attn_kernel()
{
    extern __shared__ float smf[];
    float (*Qs)[APAD]  = (float(*)[APAD])smf;
    float (*KPs)[APAD] = (float(*)[APAD])(smf + 128 * APAD);
    float (*Vs)[APAD]  = (float(*)[APAD])(smf + 256 * APAD);

    const int bh = blockIdx.y;
    const int b  = bh / NHEAD;
    const int h  = bh - b * NHEAD;
    const int i0 = blockIdx.x * 128;
    const int tid = threadIdx.x;
    const int tm0 = (tid >> 4) * 8;
    const int tn0 = (tid & 15) * 4;
    const float scale = 0.125f;

    const float* qb = g_q + (size_t)bh * SEQ * HDIM;
    const float* kb = g_k + (size_t)bh * SEQ * HDIM;
    const float* vb = g_v + (size_t)bh * SEQ * HDIM;

#pragma unroll
    for (int it = 0; it < 8; it++) {
        int id  = tid + it * 256;
        int row = id >> 4, c4 = id & 15;
        int n   = i0 + row;
        float4 v = make_float4(0.f, 0.f, 0.f, 0.f);
        if (n < SEQ) v = *(const float4*)(qb + (size_t)n * HDIM + c4 * 4);
        v.x *= scale; v.y *= scale; v.z *= scale; v.w *= scale;
        *(float4*)&Qs[row][c4 * 4] = v;
    }

    float acc[8][4], m_i[8], l_i[8];
#pragma unroll
    for (int i = 0; i < 8; i++) {
        m_i[i] = -INFINITY; l_i[i] = 0.f;
        acc[i][0] = acc[i][1] = acc[i][2] = acc[i][3] = 0.f;
    }

    for (int j0 = 0; j0 < SEQ; j0 += 64) {
        __syncthreads();
#pragma unroll
        for (int it = 0; it < 4; it++) {
            int id  = tid + it * 256;
            int row = id >> 4, c4 = id & 15;
            int n   = j0 + row;
            float4 kv = make_float4(0.f, 0.f, 0.f, 0.f);
            float4 vv = kv;
            if (n < SEQ) {
                kv = *(const float4*)(kb + (size_t)n * HDIM + c4 * 4);
                vv = *(const float4*)(vb + (size_t)n * HDIM + c4 * 4);
            }
            *(float4*)&KPs[row][c4 * 4] = kv;
            *(float4*)&Vs[row][c4 * 4]  = vv;
        }
        __syncthreads();

        float s[8][4];
#pragma unroll
        for (int i = 0; i < 8; i++) s[i][0] = s[i][1] = s[i][2] = s[i][3] = 0.f;

#pragma unroll
        for (int d4 = 0; d4 < 16; d4++) {
            float4 k0r = *(const float4*)&KPs[tn0 + 0][d4 * 4];
            float4 k1r = *(const float4*)&KPs[tn0 + 1][d4 * 4];
            float4 k2r = *(const float4*)&KPs[tn0 + 2][d4 * 4];
            float4 k3r = *(const float4*)&KPs[tn0 + 3][d4 * 4];
#pragma unroll
            for (int i = 0; i < 8; i++) {
                float4 q = *(const float4*)&Qs[tm0 + i][d4 * 4];
                s[i][0] += q.x*k0r.x + q.y*k0r.y + q.z*k0r.z + q.w*k0r.w;
                s[i][1] += q.x*k1r.x + q.y*k1r.y + q.z*k1r.z + q.w*k1r.w;
                s[i][2] += q.x*k2r.x + q.y*k2r.y + q.z*k2r.z + q.w*k2r.w;
                s[i][3] += q.x*k3r.x + q.y*k3r.y + q.z*k3r.z + q.w*k3r.w;
            }
        }

        const bool tail = (j0 + 64 > SEQ);
#pragma unroll
        for (int i = 0; i < 8; i++) {
            if (tail) {
#pragma unroll
                for (int j = 0; j < 4; j++)
                    if (j0 + tn0 + j >= SEQ) s[i][j] = -INFINITY;
            }
            float mx = fmaxf(fmaxf(s[i][0], s[i][1]), fmaxf(s[i][2], s[i][3]));
            mx = fmaxf(mx, __shfl_xor_sync(0xffffffffu, mx, 1));
            mx = fmaxf(mx, __shfl_xor_sync(0xffffffffu, mx, 2));
            mx = fmaxf(mx, __shfl_xor_sync(0xffffffffu, mx, 4));
            mx = fmaxf(mx, __shfl_xor_sync(0xffffffffu, mx, 8));
            float mnew = fmaxf(m_i[i], mx);
            float corr = __expf(m_i[i] - mnew);
            float rs = 0.f;
#pragma unroll
            for (int j = 0; j < 4; j++) {
                float pv = __expf(s[i][j] - mnew);
                s[i][j] = pv; rs += pv;
            }
            rs += __shfl_xor_sync(0xffffffffu, rs, 1);
            rs += __shfl_xor_sync(0xffffffffu, rs, 2);
            rs += __shfl_xor_sync(0xffffffffu, rs, 4);
            rs += __shfl_xor_sync(0xffffffffu, rs, 8);
            l_i[i] = l_i[i] * corr + rs;
            m_i[i] = mnew;
            acc[i][0] *= corr; acc[i][1] *= corr;
            acc[i][2] *= corr; acc[i][3] *= corr;
        }

        __syncthreads();
#pragma unroll
        for (int i = 0; i < 8; i++)
            *(float4*)&KPs[tm0 + i][tn0] = make_float4(s[i][0], s[i][1], s[i][2], s[i][3]);
        __syncthreads();

#pragma unroll
        for (int c4 = 0; c4 < 16; c4++) {
            float4 v0 = *(const float4*)&Vs[c4 * 4 + 0][tn0];
            float4 v1 = *(const float4*)&Vs[c4 * 4 + 1][tn0];
            float4 v2 = *(const float4*)&Vs[c4 * 4 + 2][tn0];
            float4 v3 = *(const float4*)&Vs[c4 * 4 + 3][tn0];
#pragma unroll
            for (int i = 0; i < 8; i++) {
                float4 pv = *(const float4*)&KPs[tm0 + i][c4 * 4];
                acc[i][0] += pv.x*v0.x + pv.y*v1.x + pv.z*v2.x + pv.w*v3.x;
                acc[i][1] += pv.x*v0.y + pv.y*v1.y + pv.z*v2.y + pv.w*v3.y;
                acc[i][2] += pv.x*v0.z + pv.y*v1.z + pv.z*v2.z + pv.w*v3.z;
                acc[i][3] += pv.x*v0.w + pv.y*v1.w + pv.z*v2.w + pv.w*v3.w;
            }
        }
    }

    // Epilogue: write O as bf16 hi/lo (A operand of the out-projection GEMM)
#pragma unroll
    for (int i = 0; i < 8; i++) {
        int n = i0 + tm0 + i;
        if (n < SEQ) {
            float inv = 1.0f / l_i[i];
            float v0 = acc[i][0]*inv, v1 = acc[i][1]*inv;
            float v2 = acc[i][2]*inv, v3 = acc[i][3]*inv;
            __nv_bfloat16 h0 = __float2bfloat16(v0), h1 = __float2bfloat16(v1);
            __nv_bfloat16 h2 = __float2bfloat16(v2), h3 = __float2bfloat16(v3);
            __nv_bfloat16 l0 = __float2bfloat16(v0 - __bfloat162float(h0));
            __nv_bfloat16 l1 = __float2bfloat16(v1 - __bfloat162float(h1));
            __nv_bfloat16 l2 = __float2bfloat16(v2 - __bfloat162float(h2));
            __nv_bfloat16 l3 = __float2bfloat16(v3 - __bfloat162float(h3));
            size_t o = ((size_t)b * SEQ + n) * DIMV + h * HDIM + tn0;
            *(__nv_bfloat162*)(g_ah + o)     = __halves2bfloat162(h0, h1);
            *(__nv_bfloat162*)(g_ah + o + 2) = __halves2bfloat162(h2, h3);
            *(__nv_bfloat162*)(g_al + o)     = __halves2bfloat162(l0, l1);
            *(__nv_bfloat162*)(g_al + o + 2) = __halves2bfloat162(l2, l3);
        }
    }
}

// ---------------------------------------------------------------------------
extern "C" void kernel_launch(void* const* d_in, const int* in_sizes, int n_in,
                              void* d_out, int out_size)
{
    const float* x    = (const float*)d_in[0];
    const float* Wqkv = (const float*)d_in[1];
    const float* bqkv = (const float*)d_in[2];
    const float* Wo   = (const float*)d_in[3];
    const float* bo   = (const float*)d_in[4];
    float* out = (float*)d_out;

    __nv_bfloat16 *xh, *xl, *wqh, *wql, *woh, *wol, *ah, *al;
    cudaGetSymbolAddress((void**)&xh,  g_xh);
    cudaGetSymbolAddress((void**)&xl,  g_xl);
    cudaGetSymbolAddress((void**)&wqh, g_wqh);
    cudaGetSymbolAddress((void**)&wql, g_wql);
    cudaGetSymbolAddress((void**)&woh, g_woh);
    cudaGetSymbolAddress((void**)&wol, g_wol);
    cudaGetSymbolAddress((void**)&ah,  g_ah);
    cudaGetSymbolAddress((void**)&al,  g_al);

    cudaFuncSetAttribute(bgemm_kernel<1>, cudaFuncAttributeMaxDynamicSharedMemorySize, GEMM_SMEM);
    cudaFuncSetAttribute(bgemm_kernel<0>, cudaFuncAttributeMaxDynamicSharedMemorySize, GEMM_SMEM);
    cudaFuncSetAttribute(attn_kernel, cudaFuncAttributeMaxDynamicSharedMemorySize, (int)ATTN_SMEM);

    // 1) splits: x -> bf16 hi/lo; weights -> transposed bf16 hi/lo
    split_x_kernel<<<(TOK * DIMV / 4) / 256, 256>>>((const float4*)x,
                                                    (__nv_bfloat162*)xh, (__nv_bfloat162*)xl,
                                                    TOK * DIMV / 4);
    tsplit_kernel<<<dim3(F3 / 32, DIMV / 32), 256>>>(Wqkv, wqh, wql, DIMV, F3);
    tsplit_kernel<<<dim3(DIMV / 32, DIMV / 32), 256>>>(Wo, woh, wol, DIMV, DIMV);

    // 2) QKV projection (mma.sync tensor cores) + scatter into q/k/v
    bgemm_kernel<1><<<dim3(F3 / 128, TOK / 128), 256, GEMM_SMEM>>>(
        xh, xl, wqh, wql, bqkv, nullptr, DIMV);

    // 3) Flash attention (SIMT fp32)
    attn_kernel<<<dim3((SEQ + 127) / 128, BATCH * NHEAD), 256, ATTN_SMEM>>>();

    // 4) Output projection (mma.sync tensor cores)
    bgemm_kernel<0><<<dim3(DIMV / 128, TOK / 128), 256, GEMM_SMEM>>>(
        ah, al, woh, wol, bo, out, DIMV);
}

// round 10
// speedup vs baseline: 2.8181x; 2.0320x over previous
#include <cuda_runtime.h>
#include <cuda_bf16.h>
#include <cstdint>
#include <math.h>

#define BATCH 16
#define SEQ   784
#define DIMV  768
#define NHEAD 12
#define HDIM  64
#define TOK   (BATCH*SEQ)   // 12544
#define F3    (3*DIMV)      // 2304

// ---------------- scratch (device globals; allocation-free) ----------------
__device__ __align__(16) __nv_bfloat16 g_xh[(size_t)TOK*DIMV];
__device__ __align__(16) __nv_bfloat16 g_xl[(size_t)TOK*DIMV];
__device__ __align__(16) __nv_bfloat16 g_wqh[(size_t)F3*DIMV];   // [2304][768] (transposed)
__device__ __align__(16) __nv_bfloat16 g_wql[(size_t)F3*DIMV];
__device__ __align__(16) __nv_bfloat16 g_woh[(size_t)DIMV*DIMV]; // [768][768] (transposed)
__device__ __align__(16) __nv_bfloat16 g_wol[(size_t)DIMV*DIMV];
__device__ __align__(16) __nv_bfloat16 g_ah[(size_t)TOK*DIMV];   // attention out hi
__device__ __align__(16) __nv_bfloat16 g_al[(size_t)TOK*DIMV];   // attention out lo
// packed bf16 hi|lo<<16 per element
__device__ __align__(16) uint32_t g_qp[(size_t)BATCH*NHEAD*SEQ*HDIM];  // [b][h][n][d]
__device__ __align__(16) uint32_t g_kp[(size_t)BATCH*NHEAD*SEQ*HDIM];  // [b][h][n][d]
__device__ __align__(16) uint32_t g_vp[(size_t)BATCH*NHEAD*HDIM*SEQ];  // [b][h][d][n] (transposed)

// ---------------- helpers (baseline PTX only: sm_80+ features) -------------
__device__ __forceinline__ uint32_t smem_u32(const void* p) {
    uint32_t a;
    asm("{ .reg .u64 t; cvta.to.shared.u64 t, %1; cvt.u32.u64 %0, t; }" : "=r"(a) : "l"(p));
    return a;
}
__device__ __forceinline__ void cp_async16(uint32_t dst, const void* src) {
    asm volatile("cp.async.cg.shared.global [%0], [%1], 16;" :: "r"(dst), "l"(src));
}
__device__ __forceinline__ void cp_async16z(uint32_t dst, const void* src, uint32_t sz) {
    asm volatile("cp.async.cg.shared.global [%0], [%1], 16, %2;" :: "r"(dst), "l"(src), "r"(sz));
}
__device__ __forceinline__ void cp_commit() {
    asm volatile("cp.async.commit_group;" ::: "memory");
}
template<int N>
__device__ __forceinline__ void cp_wait() {
    asm volatile("cp.async.wait_group %0;" :: "n"(N) : "memory");
}
__device__ __forceinline__ uint32_t lds32(uint32_t addr) {
    uint32_t v;
    asm volatile("ld.shared.b32 %0, [%1];" : "=r"(v) : "r"(addr));
    return v;
}
// D = A(16x16 bf16, row) * B(16x8 bf16, col) + D  (fp32 accum)
__device__ __forceinline__ void mma16816(float* c, const uint32_t* a, uint32_t b0, uint32_t b1) {
    asm volatile(
        "mma.sync.aligned.m16n8k16.row.col.f32.bf16.bf16.f32 "
        "{%0,%1,%2,%3}, {%4,%5,%6,%7}, {%8,%9}, {%0,%1,%2,%3};"
        : "+f"(c[0]), "+f"(c[1]), "+f"(c[2]), "+f"(c[3])
        : "r"(a[0]), "r"(a[1]), "r"(a[2]), "r"(a[3]), "r"(b0), "r"(b1));
}
// split fp32 into packed (hi | lo<<16) bf16 pair
__device__ __forceinline__ uint32_t pksplit(float v) {
    __nv_bfloat16 h = __float2bfloat16(v);
    float hf = __bfloat162float(h);
    __nv_bfloat16 l = __float2bfloat16(v - hf);
    return (uint32_t)__bfloat16_as_ushort(h) | ((uint32_t)__bfloat16_as_ushort(l) << 16);
}
// pack two fp32 -> bf16x2 (lo = a, hi = b)
__device__ __forceinline__ uint32_t pack2(float a, float b) {
    __nv_bfloat162 t = __floats2bfloat162_rn(a, b);   // x = a (low), y = b (high)
    return *(uint32_t*)&t;
}

// ---------------------------------------------------------------------------
// Split kernels: fp32 -> bf16 hi/lo (residual) pairs
// ---------------------------------------------------------------------------
__global__ __launch_bounds__(256)
void split_x_kernel(const float4* __restrict__ x,
                    __nv_bfloat162* __restrict__ xh, __nv_bfloat162* __restrict__ xl, int n4)
{
    int i = blockIdx.x * 256 + threadIdx.x;
    if (i >= n4) return;
    float4 v = x[i];
    __nv_bfloat16 h0 = __float2bfloat16(v.x), h1 = __float2bfloat16(v.y);
    __nv_bfloat16 h2 = __float2bfloat16(v.z), h3 = __float2bfloat16(v.w);
    __nv_bfloat16 l0 = __float2bfloat16(v.x - __bfloat162float(h0));
    __nv_bfloat16 l1 = __float2bfloat16(v.y - __bfloat162float(h1));
    __nv_bfloat16 l2 = __float2bfloat16(v.z - __bfloat162float(h2));
    __nv_bfloat16 l3 = __float2bfloat16(v.w - __bfloat162float(h3));
    xh[2*i]   = __halves2bfloat162(h0, h1);
    xh[2*i+1] = __halves2bfloat162(h2, h3);
    xl[2*i]   = __halves2bfloat162(l0, l1);
    xl[2*i+1] = __halves2bfloat162(l2, l3);
}

// W [K_][N_] fp32 -> Th/Tl [N_][K_] bf16 (transpose + split)
__global__ __launch_bounds__(256)
void tsplit_kernel(const float* __restrict__ W,
                   __nv_bfloat16* __restrict__ Th, __nv_bfloat16* __restrict__ Tl,
                   int K_, int N_)
{
    __shared__ float t[32][33];
    int n0 = blockIdx.x * 32, k0 = blockIdx.y * 32;
    int tx = threadIdx.x & 31, ty = threadIdx.x >> 5;
#pragma unroll
    for (int r = 0; r < 4; r++)
        t[ty + r*8][tx] = W[(size_t)(k0 + ty + r*8) * N_ + n0 + tx];
    __syncthreads();
#pragma unroll
    for (int r = 0; r < 4; r++) {
        float v = t[tx][ty + r*8];
        __nv_bfloat16 h = __float2bfloat16(v);
        __nv_bfloat16 l = __float2bfloat16(v - __bfloat162float(h));
        size_t o = (size_t)(n0 + ty + r*8) * K_ + k0 + tx;
        Th[o] = h; Tl[o] = l;
    }
}

// ---------------------------------------------------------------------------
// mma.sync bf16x3 GEMM: C[128,128-tile] = A @ B^T + bias (fp32-accurate).
// SCATTER=1: QKV epilogue writing packed-u32 Q/K ([b][h][n][d]) and
//            transposed packed V ([b][h][d][n]).
// ---------------------------------------------------------------------------
#define GBK     32
#define NCHUNK  (DIMV / GBK)          // 24
#define ROWB    80                    // 32 bf16 (64B) + 16B pad
#define TILE_B  (128 * ROWB)          // 10240
#define STAGE_B (4 * TILE_B)          // 40960: Ah, Al, Bh, Bl
#define GEMM_SMEM (2 * STAGE_B)       // 81920

template<int SCATTER>
__global__ __launch_bounds__(256)
void bgemm_kernel(const __nv_bfloat16* __restrict__ Ah, const __nv_bfloat16* __restrict__ Al,
                  const __nv_bfloat16* __restrict__ Bh, const __nv_bfloat16* __restrict__ Bl,
                  const float* __restrict__ bias, float* __restrict__ C, int K)
{
    extern __shared__ char sm[];
    const uint32_t sb = smem_u32(sm);
    const int tid  = threadIdx.x;
    const int wid  = tid >> 5, lane = tid & 31;
    const int wm   = wid & 3, wn = wid >> 2;      // 4 x 2 warp grid
    const int tr   = lane >> 2;                   // 0..7
    const int tc   = (lane & 3) * 2;              // 0,2,4,6
    const int bm   = blockIdx.y * 128, bn = blockIdx.x * 128;

    const __nv_bfloat16* bases[4] = {
        Ah + (size_t)bm * K, Al + (size_t)bm * K,
        Bh + (size_t)bn * K, Bl + (size_t)bn * K };

    auto issue = [&](int c, int p) {
        const int k0 = c * GBK;
#pragma unroll
        for (int t = 0; t < 4; t++) {
#pragma unroll
            for (int i = 0; i < 2; i++) {
                int idx = tid + i * 256;          // 0..511
                int row = idx >> 2, c8 = idx & 3; // 128 rows x 4 x (8 bf16)
                cp_async16(sb + p * STAGE_B + t * TILE_B + row * ROWB + c8 * 16,
                           bases[t] + (size_t)row * K + k0 + c8 * 8);
            }
        }
        cp_commit();
    };

    float acc[2][8][4];
#pragma unroll
    for (int mi = 0; mi < 2; mi++)
#pragma unroll
        for (int ni = 0; ni < 8; ni++)
#pragma unroll
            for (int j = 0; j < 4; j++) acc[mi][ni][j] = 0.f;

    issue(0, 0);

    for (int c = 0; c < NCHUNK; c++) {
        const int p = c & 1;
        if (c + 1 < NCHUNK) { issue(c + 1, p ^ 1); cp_wait<1>(); }
        else                { cp_wait<0>(); }
        __syncthreads();

        const uint32_t stg = sb + p * STAGE_B;
#pragma unroll
        for (int k16 = 0; k16 < GBK; k16 += 16) {
            uint32_t ah[2][4], al[2][4];
#pragma unroll
            for (int mi = 0; mi < 2; mi++) {
                const int m = wm * 32 + mi * 16;
                const uint32_t o00 = stg + (m + tr)     * ROWB + (k16 + tc) * 2;
                const uint32_t o10 = stg + (m + tr + 8) * ROWB + (k16 + tc) * 2;
                ah[mi][0] = lds32(o00);
                ah[mi][1] = lds32(o10);
                ah[mi][2] = lds32(o00 + 16);
                ah[mi][3] = lds32(o10 + 16);
                al[mi][0] = lds32(o00 + TILE_B);
                al[mi][1] = lds32(o10 + TILE_B);
                al[mi][2] = lds32(o00 + 16 + TILE_B);
                al[mi][3] = lds32(o10 + 16 + TILE_B);
            }
#pragma unroll
            for (int ni = 0; ni < 8; ni++) {
                const int n = wn * 64 + ni * 8;
                const uint32_t ob = stg + 2 * TILE_B + (n + tr) * ROWB + (k16 + tc) * 2;
                uint32_t bh0 = lds32(ob),          bh1 = lds32(ob + 16);
                uint32_t bl0 = lds32(ob + TILE_B), bl1 = lds32(ob + TILE_B + 16);
#pragma unroll
                for (int mi = 0; mi < 2; mi++) {
                    mma16816(acc[mi][ni], ah[mi], bh0, bh1);
                    mma16816(acc[mi][ni], al[mi], bh0, bh1);
                    mma16816(acc[mi][ni], ah[mi], bl0, bl1);
                }
            }
        }
        __syncthreads();
    }

#pragma unroll
    for (int mi = 0; mi < 2; mi++) {
#pragma unroll
        for (int ni = 0; ni < 8; ni++) {
            const int r0  = bm + wm * 32 + mi * 16 + tr;
            const int col = bn + wn * 64 + ni * 8 + tc;
            const float b0 = bias[col], b1 = bias[col + 1];
            float2 v0 = make_float2(acc[mi][ni][0] + b0, acc[mi][ni][1] + b1);
            float2 v1 = make_float2(acc[mi][ni][2] + b0, acc[mi][ni][3] + b1);
            if (SCATTER) {
                int s   = col / DIMV;
                int rem = col - s * DIMV;
                int hh  = rem >> 6, d0 = rem & 63;
                int bb0 = r0 / SEQ,       n0 = r0 - bb0 * SEQ;
                int bb1 = (r0 + 8) / SEQ, n1 = (r0 + 8) - bb1 * SEQ;
                if (s < 2) {
                    uint32_t* base = (s == 0) ? g_qp : g_kp;
                    uint2 u0 = make_uint2(pksplit(v0.x), pksplit(v0.y));
                    uint2 u1 = make_uint2(pksplit(v1.x), pksplit(v1.y));
                    *(uint2*)(base + (((size_t)bb0 * NHEAD + hh) * SEQ + n0) * HDIM + d0) = u0;
                    *(uint2*)(base + (((size_t)bb1 * NHEAD + hh) * SEQ + n1) * HDIM + d0) = u1;
                } else {
                    uint32_t* vb0 = g_vp + (((size_t)bb0 * NHEAD + hh) * HDIM + d0) * SEQ;
                    uint32_t* vb1 = g_vp + (((size_t)bb1 * NHEAD + hh) * HDIM + d0) * SEQ;
                    vb0[n0]       = pksplit(v0.x);
                    vb0[SEQ + n0] = pksplit(v0.y);
                    vb1[n1]       = pksplit(v1.x);
                    vb1[SEQ + n1] = pksplit(v1.y);
                }
            } else {
                *(float2*)(C + (size_t)r0 * DIMV + col)       = v0;
                *(float2*)(C + (size_t)(r0 + 8) * DIMV + col) = v1;
            }
        }
    }
}

// ---------------------------------------------------------------------------
// Flash attention with mma.sync bf16x3.
// CTA: 128 i-rows (8 warps x 16 rows), j-tiles of 64, double-buffered cp.async.
// K packed [b][h][n][d], V packed transposed [b][h][d][n] (both u32 hi|lo).
// Stage layout: [K tile: VTILE u32][V tile: VTILE u32]  (V offset = VTILE*4 !)
// ---------------------------------------------------------------------------
#define NJT   13                         // ceil(784/64)
#define KP    68                         // u32 pitch per 64-col tile row
#define VTILE (64 * KP)                  // u32 per tile (4352)
#define STAGE_U (2 * VTILE)              // K tile + V tile (u32 count)
#define ATTN_SMEM (2 * STAGE_U * 4)      // 69632 bytes

__global__ __launch_bounds__(256)
void attn_mma_kernel()
{
    extern __shared__ uint32_t smu[];
    const uint32_t sb = smem_u32(smu);
    const int tid = threadIdx.x;
    const int wid = tid >> 5, lane = tid & 31;
    const int tr  = lane >> 2;            // 0..7
    const int tc2 = (lane & 3) * 2;       // 0,2,4,6
    const int bh  = blockIdx.y;
    const int b   = bh / NHEAD;
    const int h   = bh - b * NHEAD;
    const int i0  = blockIdx.x * 128;

    const uint32_t* qp = g_qp + (size_t)bh * SEQ * HDIM;
    const uint32_t* kp = g_kp + (size_t)bh * SEQ * HDIM;
    const uint32_t* vp = g_vp + (size_t)bh * HDIM * SEQ;

    // ---- Q fragments once into registers (hi & lo) ----
    uint32_t qh[4][4], ql[4][4];
    {
        const int r0 = i0 + wid * 16 + tr;
#pragma unroll
        for (int kc = 0; kc < 4; kc++) {
#pragma unroll
            for (int ii = 0; ii < 4; ii++) {
                int row = r0 + (ii & 1) * 8;
                int col = kc * 16 + tc2 + (ii >> 1) * 8;
                uint2 e = make_uint2(0u, 0u);
                if (row < SEQ) e = *(const uint2*)(qp + (size_t)row * HDIM + col);
                qh[kc][ii] = __byte_perm(e.x, e.y, 0x5410);
                ql[kc][ii] = __byte_perm(e.x, e.y, 0x7632);
            }
        }
    }

    auto issue = [&](int jt, int p) {
        const int j0 = jt * 64;
        const uint32_t base = sb + p * STAGE_U * 4;
#pragma unroll
        for (int i = 0; i < 4; i++) {
            int cid = tid + i * 256;         // 0..1023
            int row = cid >> 4, ch = cid & 15;
            // K tile row = j index
            {
                int n = j0 + row;
                uint32_t sz = (n < SEQ) ? 16u : 0u;
                const uint32_t* src = kp + (size_t)(n < SEQ ? n : 0) * HDIM + ch * 4;
                cp_async16z(base + (row * KP + ch * 4) * 4, src, sz);
            }
            // V tile row = d index, cols = j  (offset within stage = VTILE*4)
            {
                int jc = j0 + ch * 4;
                uint32_t sz = (jc < SEQ) ? 16u : 0u;
                const uint32_t* src = vp + (size_t)row * SEQ + (jc < SEQ ? jc : 0);
                cp_async16z(base + VTILE * 4 + (row * KP + ch * 4) * 4, src, sz);
            }
        }
        cp_commit();
    };

    float acc[8][4];
#pragma unroll
    for (int n8 = 0; n8 < 8; n8++)
#pragma unroll
        for (int j = 0; j < 4; j++) acc[n8][j] = 0.f;
    float m0 = -1e30f, m1 = -1e30f, l0 = 0.f, l1 = 0.f;

    issue(0, 0);

    for (int jt = 0; jt < NJT; jt++) {
        const int p = jt & 1;
        if (jt + 1 < NJT) { issue(jt + 1, p ^ 1); cp_wait<1>(); }
        else              { cp_wait<0>(); }
        __syncthreads();

        const uint32_t kb = sb + p * STAGE_U * 4;
        const uint32_t vb = kb + VTILE * 4;

        // ---- S = Q @ K^T (bf16x3) ----
        float c[8][4];
#pragma unroll
        for (int n8 = 0; n8 < 8; n8++)
#pragma unroll
            for (int j = 0; j < 4; j++) c[n8][j] = 0.f;

#pragma unroll
        for (int kc = 0; kc < 4; kc++) {
#pragma unroll
            for (int n8 = 0; n8 < 8; n8++) {
                const uint32_t ko = kb + ((n8 * 8 + tr) * KP + kc * 16 + tc2) * 4;
                uint32_t e0x = lds32(ko),      e0y = lds32(ko + 4);
                uint32_t e1x = lds32(ko + 32), e1y = lds32(ko + 36);
                uint32_t bh0 = __byte_perm(e0x, e0y, 0x5410);
                uint32_t bl0 = __byte_perm(e0x, e0y, 0x7632);
                uint32_t bh1 = __byte_perm(e1x, e1y, 0x5410);
                uint32_t bl1 = __byte_perm(e1x, e1y, 0x7632);
                mma16816(c[n8], qh[kc], bh0, bh1);
                mma16816(c[n8], ql[kc], bh0, bh1);
                mma16816(c[n8], qh[kc], bl0, bl1);
            }
        }

        // scale + tail mask
#pragma unroll
        for (int n8 = 0; n8 < 8; n8++)
#pragma unroll
            for (int j = 0; j < 4; j++) c[n8][j] *= 0.125f;
        if (jt == NJT - 1) {
#pragma unroll
            for (int n8 = 2; n8 < 8; n8++)
#pragma unroll
                for (int j = 0; j < 4; j++) c[n8][j] = -1e30f;
        }

        // ---- online softmax (rows tr and tr+8; each row spans 4 lanes) ----
        float mx0 = -1e30f, mx1 = -1e30f;
#pragma unroll
        for (int n8 = 0; n8 < 8; n8++) {
            mx0 = fmaxf(mx0, fmaxf(c[n8][0], c[n8][1]));
            mx1 = fmaxf(mx1, fmaxf(c[n8][2], c[n8][3]));
        }
        mx0 = fmaxf(mx0, __shfl_xor_sync(0xffffffffu, mx0, 1));
        mx0 = fmaxf(mx0, __shfl_xor_sync(0xffffffffu, mx0, 2));
        mx1 = fmaxf(mx1, __shfl_xor_sync(0xffffffffu, mx1, 1));
        mx1 = fmaxf(mx1, __shfl_xor_sync(0xffffffffu, mx1, 2));
        float mn0 = fmaxf(m0, mx0), mn1 = fmaxf(m1, mx1);
        float cr0 = __expf(m0 - mn0), cr1 = __expf(m1 - mn1);
        float rs0 = 0.f, rs1 = 0.f;
#pragma unroll
        for (int n8 = 0; n8 < 8; n8++) {
            c[n8][0] = __expf(c[n8][0] - mn0); rs0 += c[n8][0];
            c[n8][1] = __expf(c[n8][1] - mn0); rs0 += c[n8][1];
            c[n8][2] = __expf(c[n8][2] - mn1); rs1 += c[n8][2];
            c[n8][3] = __expf(c[n8][3] - mn1); rs1 += c[n8][3];
        }
        rs0 += __shfl_xor_sync(0xffffffffu, rs0, 1);
        rs0 += __shfl_xor_sync(0xffffffffu, rs0, 2);
        rs1 += __shfl_xor_sync(0xffffffffu, rs1, 1);
        rs1 += __shfl_xor_sync(0xffffffffu, rs1, 2);
        l0 = l0 * cr0 + rs0; m0 = mn0;
        l1 = l1 * cr1 + rs1; m1 = mn1;
#pragma unroll
        for (int n8 = 0; n8 < 8; n8++) {
            acc[n8][0] *= cr0; acc[n8][1] *= cr0;
            acc[n8][2] *= cr1; acc[n8][3] *= cr1;
        }

        // ---- O += P @ V (bf16x3); P a-frags straight from c registers ----
#pragma unroll
        for (int kc = 0; kc < 4; kc++) {
            uint32_t pa_h[4], pa_l[4];
#pragma unroll
            for (int ii = 0; ii < 4; ii++) {
                // ii: 0->(c[2kc][0],[1]) 1->(c[2kc][2],[3]) 2->(c[2kc+1][0],[1]) 3->(c[2kc+1][2],[3])
                int f = 2 * kc + (ii >> 1);
                float p0 = c[f][(ii & 1) * 2], p1 = c[f][(ii & 1) * 2 + 1];
                uint32_t hp = pack2(p0, p1);
                pa_h[ii] = hp;
                float h0 = __uint_as_float(hp << 16);
                float h1 = __uint_as_float(hp & 0xFFFF0000u);
                pa_l[ii] = pack2(p0 - h0, p1 - h1);
            }
#pragma unroll
            for (int n8 = 0; n8 < 8; n8++) {
                const uint32_t vo = vb + ((n8 * 8 + tr) * KP + kc * 16 + tc2) * 4;
                uint32_t e0x = lds32(vo),      e0y = lds32(vo + 4);
                uint32_t e1x = lds32(vo + 32), e1y = lds32(vo + 36);
                uint32_t vh0 = __byte_perm(e0x, e0y, 0x5410);
                uint32_t vl0 = __byte_perm(e0x, e0y, 0x7632);
                uint32_t vh1 = __byte_perm(e1x, e1y, 0x5410);
                uint32_t vl1 = __byte_perm(e1x, e1y, 0x7632);
                mma16816(acc[n8], pa_h, vh0, vh1);
                mma16816(acc[n8], pa_l, vh0, vh1);
                mma16816(acc[n8], pa_h, vl0, vl1);
            }
        }
        __syncthreads();
    }

    // ---- epilogue: normalize, split to bf16 hi/lo, write [b][n][h*64+d] ----
    const float inv0 = 1.0f / l0, inv1 = 1.0f / l1;
    const int n0 = i0 + wid * 16 + tr, n1 = n0 + 8;
#pragma unroll
    for (int n8 = 0; n8 < 8; n8++) {
        int d = h * HDIM + n8 * 8 + tc2;
        if (n0 < SEQ) {
            float v0 = acc[n8][0] * inv0, v1 = acc[n8][1] * inv0;
            uint32_t hp = pack2(v0, v1);
            float h0 = __uint_as_float(hp << 16), h1 = __uint_as_float(hp & 0xFFFF0000u);
            uint32_t lp = pack2(v0 - h0, v1 - h1);
            size_t o = ((size_t)b * SEQ + n0) * DIMV + d;
            *(uint32_t*)(g_ah + o) = hp;
            *(uint32_t*)(g_al + o) = lp;
        }
        if (n1 < SEQ) {
            float v0 = acc[n8][2] * inv1, v1 = acc[n8][3] * inv1;
            uint32_t hp = pack2(v0, v1);
            float h0 = __uint_as_float(hp << 16), h1 = __uint_as_float(hp & 0xFFFF0000u);
            uint32_t lp = pack2(v0 - h0, v1 - h1);
            size_t o = ((size_t)b * SEQ + n1) * DIMV + d;
            *(uint32_t*)(g_ah + o) = hp;
            *(uint32_t*)(g_al + o) = lp;
        }
    }
}

// ---------------------------------------------------------------------------
extern "C" void kernel_launch(void* const* d_in, const int* in_sizes, int n_in,
                              void* d_out, int out_size)
{
    const float* x    = (const float*)d_in[0];
    const float* Wqkv = (const float*)d_in[1];
    const float* bqkv = (const float*)d_in[2];
    const float* Wo   = (const float*)d_in[3];
    const float* bo   = (const float*)d_in[4];
    float* out = (float*)d_out;

    __nv_bfloat16 *xh, *xl, *wqh, *wql, *woh, *wol, *ah, *al;
    cudaGetSymbolAddress((void**)&xh,  g_xh);
    cudaGetSymbolAddress((void**)&xl,  g_xl);
    cudaGetSymbolAddress((void**)&wqh, g_wqh);
    cudaGetSymbolAddress((void**)&wql, g_wql);
    cudaGetSymbolAddress((void**)&woh, g_woh);
    cudaGetSymbolAddress((void**)&wol, g_wol);
    cudaGetSymbolAddress((void**)&ah,  g_ah);
    cudaGetSymbolAddress((void**)&al,  g_al);

    cudaFuncSetAttribute(bgemm_kernel<1>, cudaFuncAttributeMaxDynamicSharedMemorySize, GEMM_SMEM);
    cudaFuncSetAttribute(bgemm_kernel<0>, cudaFuncAttributeMaxDynamicSharedMemorySize, GEMM_SMEM);
    cudaFuncSetAttribute(attn_mma_kernel, cudaFuncAttributeMaxDynamicSharedMemorySize, ATTN_SMEM);

    // 1) splits: x -> bf16 hi/lo; weights -> transposed bf16 hi/lo
    split_x_kernel<<<(TOK * DIMV / 4) / 256, 256>>>((const float4*)x,
                                                    (__nv_bfloat162*)xh, (__nv_bfloat162*)xl,
                                                    TOK * DIMV / 4);
    tsplit_kernel<<<dim3(F3 / 32, DIMV / 32), 256>>>(Wqkv, wqh, wql, DIMV, F3);
    tsplit_kernel<<<dim3(DIMV / 32, DIMV / 32), 256>>>(Wo, woh, wol, DIMV, DIMV);

    // 2) QKV projection (mma.sync) scattering packed Q/K + transposed packed V
    bgemm_kernel<1><<<dim3(F3 / 128, TOK / 128), 256, GEMM_SMEM>>>(
        xh, xl, wqh, wql, bqkv, nullptr, DIMV);

    // 3) Flash attention (mma.sync bf16x3)
    attn_mma_kernel<<<dim3((SEQ + 127) / 128, BATCH * NHEAD), 256, ATTN_SMEM>>>();

    // 4) Output projection (mma.sync)
    bgemm_kernel<0><<<dim3(DIMV / 128, TOK / 128), 256, GEMM_SMEM>>>(
        ah, al, woh, wol, bo, out, DIMV);
}